// round 14
// baseline (speedup 1.0000x reference)
#include <cuda_runtime.h>
#include <cuda_fp16.h>
#include <cuda_bf16.h>
#include <cstdint>

#define D 128
#define NMAX 50000
#define EMAX 800000
#define D4 (D/4)    // 32 float4 per fp32 row
#define DH2 (D/4)   // 32 uint2 per fp16 row

// ---------------- scratch (no allocations allowed) ----------------
__device__ int    g_deg[NMAX];             // raw in-degree (no self-loop)
__device__ float  g_dinv[NMAX];            // rsqrt(deg+1)
__device__ int    g_rowstart[NMAX];
__device__ int    g_cur[NMAX];
__device__ int    g_esrc[EMAX];
__device__ int    g_total;                 // CSR slot allocator
__device__ __half g_h[(size_t)NMAX * D];   // message buffer (fp16)
__device__ float  g_a[(size_t)NMAX * D];   // layer-1 activation (fp32)
// W split into bf16 hi/lo, TRANSPOSED: buf[n*128 + k] = bf16(W[k][n])
__device__ __align__(16) __nv_bfloat16 g_wh1[16384];
__device__ __align__(16) __nv_bfloat16 g_wl1[16384];
__device__ __align__(16) __nv_bfloat16 g_wh2[16384];
__device__ __align__(16) __nv_bfloat16 g_wl2[16384];

// per-block edge-index dtype detection (int64 values < 2^31 => odd words 0)
__device__ __forceinline__ int detect_is64(const int* __restrict__ ei) {
    int all0 = 1;
    for (int j = 0; j < 64; ++j)
        if (ei[2 * j + 1] != 0) { all0 = 0; break; }
    return all0;
}

__device__ __forceinline__ int load_idx(const int* __restrict__ ei, size_t pos, int is64) {
    return is64 ? ei[2 * pos] : ei[pos];
}

__device__ __forceinline__ unsigned pack_bf2(__nv_bfloat16 lo, __nv_bfloat16 hi) {
    return ((unsigned)__bfloat16_as_ushort(hi) << 16) | __bfloat16_as_ushort(lo);
}

// ------ W hi/lo conversion blocks + degree-count blocks (one launch) ------
__global__ void k_initcount(const int* __restrict__ ei,
                            const float* __restrict__ W1, const float* __restrict__ W2,
                            int E) {
    if (blockIdx.x < 128) {
        int i = blockIdx.x * 256 + threadIdx.x;     // 0..32767
        int mat = i >> 14;                          // 0: W1, 1: W2
        int idx = i & 16383;
        const float* W = mat ? W2 : W1;
        __nv_bfloat16* WH = mat ? g_wh2 : g_wh1;
        __nv_bfloat16* WL = mat ? g_wl2 : g_wl1;
        int k = idx >> 7, j = idx & 127;
        float w = W[idx];                           // W[k][j]
        __nv_bfloat16 h = __float2bfloat16_rn(w);
        __nv_bfloat16 l = __float2bfloat16_rn(w - __bfloat162float(h));
        WH[j * 128 + k] = h;                        // transposed [n][k]
        WL[j * 128 + k] = l;
        if (blockIdx.x == 0 && threadIdx.x == 0) g_total = 0;
    } else {
        __shared__ int s_is64;
        if (threadIdx.x == 0) s_is64 = detect_is64(ei);
        __syncthreads();
        int is64 = s_is64;
        int e0 = ((int)blockIdx.x - 128) * 1024 + threadIdx.x * 4;
#pragma unroll
        for (int q = 0; q < 4; ++q) {
            int e = e0 + q;
            if (e < E) atomicAdd(&g_deg[load_idx(ei, (size_t)E + e, is64)], 1);
        }
    }
}

// ---------------- parallel CSR slot allocation + dinv ---------------------
__global__ void k_alloc(int n) {
    int i    = blockIdx.x * blockDim.x + threadIdx.x;
    int lane = threadIdx.x & 31;
    int v = (i < n) ? g_deg[i] : 0;        // edges for this node

    int pfx = v;
#pragma unroll
    for (int o = 1; o < 32; o <<= 1) {
        int t = __shfl_up_sync(0xffffffff, pfx, o);
        if (lane >= o) pfx += t;
    }
    int wtotal = __shfl_sync(0xffffffff, pfx, 31);
    int excl   = pfx - v;

    int base = 0;
    if (lane == 31) base = atomicAdd(&g_total, wtotal);
    base = __shfl_sync(0xffffffff, base, 31);

    if (i < n) {
        int run = base + excl;
        g_rowstart[i] = run;
        g_cur[i]      = run;
        g_dinv[i]     = rsqrtf((float)(v + 1));   // +1 self-loop
    }
}

// ---------------- HMMA GEMM body (2m x 4n warp grid) ----------------
#define AS 68                      // uint stride per smem row
#define SM_AH 0
#define SM_AL 4352                 // 64*68
#define SM_BH 8704
#define SM_BL 17408                // 8704 + 128*68
#define SM_UINTS 26112
#define SM_BYTES (SM_UINTS * 4)

__device__ __forceinline__ void mma_bf16(float4& d,
                                         unsigned a0, unsigned a1, unsigned a2, unsigned a3,
                                         unsigned b0, unsigned b1) {
    asm volatile(
        "mma.sync.aligned.m16n8k16.row.col.f32.bf16.bf16.f32 "
        "{%0,%1,%2,%3}, {%4,%5,%6,%7}, {%8,%9}, {%0,%1,%2,%3};"
        : "+f"(d.x), "+f"(d.y), "+f"(d.z), "+f"(d.w)
        : "r"(a0), "r"(a1), "r"(a2), "r"(a3), "r"(b0), "r"(b1));
}

__device__ __forceinline__ void gemm_body(
        int bid, unsigned* sm,
        const float* __restrict__ A,
        const __nv_bfloat16* __restrict__ WHT,
        const __nv_bfloat16* __restrict__ WLT,
        __half* __restrict__ C, int M, int scaled) {
    unsigned* AH = sm + SM_AH;
    unsigned* AL = sm + SM_AL;
    unsigned* BH = sm + SM_BH;
    unsigned* BL = sm + SM_BL;

    int tid = threadIdx.x;
    int rowBase = bid * 64;

    // ---- copy W tiles ----
    {
        const uint4* gh = (const uint4*)WHT;
        const uint4* gl = (const uint4*)WLT;
        for (int i = tid; i < 2048; i += 256) {
            int nrow = i >> 4;
            int kk   = (i & 15) * 4;
            *(uint4*)&BH[nrow * AS + kk] = gh[i];
            *(uint4*)&BL[nrow * AS + kk] = gl[i];
        }
    }

    // ---- A tile: fp32 -> bf16 hi/lo into padded smem ----
    {
        int r  = tid >> 2;
        int t4 = tid & 3;
        int rg = rowBase + r;
        const float4* A4 = (const float4*)A;
#pragma unroll
        for (int i = 0; i < 8; ++i) {
            float4 v = make_float4(0.f, 0.f, 0.f, 0.f);
            if (rg < M) v = A4[(size_t)rg * 32 + t4 * 8 + i];
            __nv_bfloat16 h0 = __float2bfloat16_rn(v.x), h1 = __float2bfloat16_rn(v.y);
            __nv_bfloat16 h2 = __float2bfloat16_rn(v.z), h3 = __float2bfloat16_rn(v.w);
            __nv_bfloat16 l0 = __float2bfloat16_rn(v.x - __bfloat162float(h0));
            __nv_bfloat16 l1 = __float2bfloat16_rn(v.y - __bfloat162float(h1));
            __nv_bfloat16 l2 = __float2bfloat16_rn(v.z - __bfloat162float(h2));
            __nv_bfloat16 l3 = __float2bfloat16_rn(v.w - __bfloat162float(h3));
            int w = r * AS + t4 * 16 + i * 2;
            AH[w]     = pack_bf2(h0, h1);
            AH[w + 1] = pack_bf2(h2, h3);
            AL[w]     = pack_bf2(l0, l1);
            AL[w + 1] = pack_bf2(l2, l3);
        }
    }
    __syncthreads();

    // ---- compute: warp grid 2m x 4n, warp tile = 32 rows x 32 cols ----
    int wid = tid >> 5, lane = tid & 31;
    int wm = wid & 1, wn = wid >> 1;
    int g = lane >> 2, tig = lane & 3;

    float4 acc[2][4];
#pragma unroll
    for (int mt = 0; mt < 2; ++mt)
#pragma unroll
        for (int nt = 0; nt < 4; ++nt) acc[mt][nt] = make_float4(0.f, 0.f, 0.f, 0.f);

#pragma unroll
    for (int ks = 0; ks < 8; ++ks) {
        int ka = ks * 8 + tig;
        unsigned ah[2][4], al[2][4];
#pragma unroll
        for (int mt = 0; mt < 2; ++mt) {
            int ar0 = (wm * 32 + mt * 16 + g) * AS;
            int ar1 = ar0 + 8 * AS;
            ah[mt][0] = AH[ar0 + ka];     ah[mt][1] = AH[ar1 + ka];
            ah[mt][2] = AH[ar0 + ka + 4]; ah[mt][3] = AH[ar1 + ka + 4];
            al[mt][0] = AL[ar0 + ka];     al[mt][1] = AL[ar1 + ka];
            al[mt][2] = AL[ar0 + ka + 4]; al[mt][3] = AL[ar1 + ka + 4];
        }
        unsigned bh[4][2], bl[4][2];
#pragma unroll
        for (int nt = 0; nt < 4; ++nt) {
            int br = (wn * 32 + nt * 8 + g) * AS + ka;
            bh[nt][0] = BH[br]; bh[nt][1] = BH[br + 4];
            bl[nt][0] = BL[br]; bl[nt][1] = BL[br + 4];
        }
#pragma unroll
        for (int mt = 0; mt < 2; ++mt)
#pragma unroll
            for (int nt = 0; nt < 4; ++nt) {
                mma_bf16(acc[mt][nt], ah[mt][0], ah[mt][1], ah[mt][2], ah[mt][3],
                         bh[nt][0], bh[nt][1]);
                mma_bf16(acc[mt][nt], al[mt][0], al[mt][1], al[mt][2], al[mt][3],
                         bh[nt][0], bh[nt][1]);
                mma_bf16(acc[mt][nt], ah[mt][0], ah[mt][1], ah[mt][2], ah[mt][3],
                         bl[nt][0], bl[nt][1]);
            }
    }

    // ---- epilogue ----
#pragma unroll
    for (int mt = 0; mt < 2; ++mt) {
        int r0 = rowBase + wm * 32 + mt * 16 + g;
        int r1 = r0 + 8;
        float s0 = 1.f, s1 = 1.f;
        if (scaled) {
            if (r0 < M) s0 = g_dinv[r0];
            if (r1 < M) s1 = g_dinv[r1];
        }
#pragma unroll
        for (int nt = 0; nt < 4; ++nt) {
            int col = wn * 32 + nt * 8 + tig * 2;
            if (r0 < M)
                *(__half2*)(C + (size_t)r0 * 128 + col) =
                    __floats2half2_rn(acc[mt][nt].x * s0, acc[mt][nt].y * s0);
            if (r1 < M)
                *(__half2*)(C + (size_t)r1 * 128 + col) =
                    __floats2half2_rn(acc[mt][nt].z * s1, acc[mt][nt].w * s1);
        }
    }
}

// ---- mega: GEMM1, then each block fills its 1024-edge CSR slice ----------
// Fill's atomic/store latency overlaps other blocks' tensor work.
__global__ __launch_bounds__(256) void k_mega(
        const float* __restrict__ A,
        const __nv_bfloat16* __restrict__ WHT,
        const __nv_bfloat16* __restrict__ WLT,
        __half* __restrict__ C, int M,
        const int* __restrict__ ei, int E) {
    extern __shared__ unsigned sm[];
    __shared__ int s_is64;

    gemm_body(blockIdx.x, sm, A, WHT, WLT, C, M, 0);

    if (threadIdx.x == 0) s_is64 = detect_is64(ei);
    __syncthreads();
    int is64 = s_is64;
    int e0 = blockIdx.x * 1024 + threadIdx.x * 4;
#pragma unroll
    for (int q = 0; q < 4; ++q) {
        int e = e0 + q;
        if (e < E) {
            int s = load_idx(ei, (size_t)e, is64);
            int d = load_idx(ei, (size_t)E + e, is64);
            int pos = atomicAdd(&g_cur[d], 1);
            g_esrc[pos] = s;
        }
    }
}

__global__ __launch_bounds__(256) void k_gemm2(
        const float* __restrict__ A,
        const __nv_bfloat16* __restrict__ WHT,
        const __nv_bfloat16* __restrict__ WLT,
        __half* __restrict__ C, int M) {
    extern __shared__ unsigned sm[];
    gemm_body(blockIdx.x, sm, A, WHT, WLT, C, M, 1);
}

// ---------------- aggregation (best measured config) ----------------------
__device__ __forceinline__ void acc_h4(float4& acc, float nm, uint2 raw) {
    __half2* ph = (__half2*)&raw;
    float2 lo = __half22float2(ph[0]);
    float2 hi = __half22float2(ph[1]);
    acc.x = fmaf(nm, lo.x, acc.x); acc.y = fmaf(nm, lo.y, acc.y);
    acc.z = fmaf(nm, hi.x, acc.z); acc.w = fmaf(nm, hi.y, acc.w);
}
__device__ __forceinline__ void add_h4(float4& acc, uint2 raw) {
    __half2* ph = (__half2*)&raw;
    float2 lo = __half22float2(ph[0]);
    float2 hi = __half22float2(ph[1]);
    acc.x += lo.x; acc.y += lo.y; acc.z += hi.x; acc.w += hi.y;
}

template<bool SCALED>
__global__ void k_agg_csr(const __half* __restrict__ H,
                          const float* __restrict__ b,
                          float* __restrict__ out, int n) {
    int warp = (int)((blockIdx.x * (size_t)blockDim.x + threadIdx.x) >> 5);
    int lane = threadIdx.x & 31;
    if (warp >= n) return;
    int node = warp;

    const uint2* H2 = (const uint2*)H;
    float di = g_dinv[node];

    float4 acc = make_float4(0, 0, 0, 0);
    {
        uint2 raw = H2[(size_t)node * DH2 + lane];
        if (SCALED) add_h4(acc, raw);
        else        acc_h4(acc, di, raw);
    }

    int p   = g_rowstart[node];
    int end = p + g_deg[node];

    for (; p + 3 < end; p += 4) {
        int s0 = g_esrc[p],   s1 = g_esrc[p+1];
        int s2 = g_esrc[p+2], s3 = g_esrc[p+3];
        uint2 v0 = H2[(size_t)s0 * DH2 + lane];
        uint2 v1 = H2[(size_t)s1 * DH2 + lane];
        uint2 v2 = H2[(size_t)s2 * DH2 + lane];
        uint2 v3 = H2[(size_t)s3 * DH2 + lane];
        if (SCALED) {
            add_h4(acc, v0); add_h4(acc, v1); add_h4(acc, v2); add_h4(acc, v3);
        } else {
            acc_h4(acc, g_dinv[s0], v0); acc_h4(acc, g_dinv[s1], v1);
            acc_h4(acc, g_dinv[s2], v2); acc_h4(acc, g_dinv[s3], v3);
        }
    }
    for (; p < end; ++p) {
        int s0 = g_esrc[p];
        uint2 v0 = H2[(size_t)s0 * DH2 + lane];
        if (SCALED) add_h4(acc, v0);
        else        acc_h4(acc, g_dinv[s0], v0);
    }

    float4 bv = ((const float4*)b)[lane];
    float4 r;
    r.x = fmaxf(fmaf(di, acc.x, bv.x), 0.f);
    r.y = fmaxf(fmaf(di, acc.y, bv.y), 0.f);
    r.z = fmaxf(fmaf(di, acc.z, bv.z), 0.f);
    r.w = fmaxf(fmaf(di, acc.w, bv.w), 0.f);
    ((float4*)out)[(size_t)node * D4 + lane] = r;
}

// ---------------- launch ----------------
extern "C" void kernel_launch(void* const* d_in, const int* in_sizes, int n_in,
                              void* d_out, int out_size) {
    const float* x  = (const float*)d_in[0];
    const int*   ei = (const int*)d_in[1];
    const float* W1 = (const float*)d_in[2];
    const float* b1 = (const float*)d_in[3];
    const float* W2 = (const float*)d_in[4];
    const float* b2 = (const float*)d_in[5];
    float* out = (float*)d_out;

    int n = in_sizes[0] / D;        // 50000
    int E = in_sizes[1] / 2;        // 800000

    __half* h;  float* a;  int* degPtr;
    __nv_bfloat16 *wh1, *wl1, *wh2, *wl2;
    cudaGetSymbolAddress((void**)&h,      g_h);
    cudaGetSymbolAddress((void**)&a,      g_a);
    cudaGetSymbolAddress((void**)&degPtr, g_deg);
    cudaGetSymbolAddress((void**)&wh1, g_wh1);
    cudaGetSymbolAddress((void**)&wl1, g_wl1);
    cudaGetSymbolAddress((void**)&wh2, g_wh2);
    cudaGetSymbolAddress((void**)&wl2, g_wl2);

    cudaFuncSetAttribute(k_mega,  cudaFuncAttributeMaxDynamicSharedMemorySize, SM_BYTES);
    cudaFuncSetAttribute(k_gemm2, cudaFuncAttributeMaxDynamicSharedMemorySize, SM_BYTES);

    int countBlocks = (E + 1023) / 1024;   // 4 edges/thread
    int aggBlocks   = (n * 32 + 255) / 256;
    int gemmBlocks  = (n + 63) / 64;       // 782 (each also fills 1024 edges)
    int nodeBlocks  = (n + 255) / 256;

    // zero degrees (captured async memset)
    cudaMemsetAsync(degPtr, 0, (size_t)n * sizeof(int));
    // W hi/lo conversion blocks + degree-count blocks
    k_initcount<<<128 + countBlocks, 256>>>(ei, W1, W2, E);
    // CSR slot allocation + dinv
    k_alloc<<<nodeBlocks, 256>>>(n);
    // GEMM1 with per-block CSR fill tail (fill hidden behind tensor work)
    k_mega<<<gemmBlocks, 256, SM_BYTES>>>(x, wh1, wl1, h, n, ei, E);
    // layer-1 aggregation (per-edge dinv)
    k_agg_csr<false><<<aggBlocks, 256>>>(h, b1, a, n);
    // layer-2 GEMM (epilogue scales rows by dinv) + pure gather-add agg
    k_gemm2<<<gemmBlocks, 256, SM_BYTES>>>(a, wh2, wl2, h, n);
    k_agg_csr<true><<<aggBlocks, 256>>>(h, b2, out, n);
}

// round 15
// speedup vs baseline: 1.0632x; 1.0632x over previous
#include <cuda_runtime.h>
#include <cuda_fp16.h>
#include <cuda_bf16.h>
#include <cstdint>

#define D 128
#define NMAX 50000
#define EMAX 800000
#define D4 (D/4)    // 32 float4 per fp32 row
#define DH2 (D/4)   // 32 uint2 per fp16 row

// ---------------- scratch (no allocations allowed) ----------------
__device__ int    g_deg[NMAX];             // raw in-degree (no self-loop)
__device__ float  g_dinv[NMAX];            // rsqrt(deg+1)
__device__ int    g_rowstart[NMAX];
__device__ int    g_cur[NMAX];
__device__ int    g_esrc[EMAX];
__device__ int    g_total;                 // CSR slot allocator
__device__ __half g_h[(size_t)NMAX * D];   // message buffer (fp16, dinv-scaled)
__device__ float  g_a[(size_t)NMAX * D];   // layer-1 activation (fp32)
// W split into bf16 hi/lo, TRANSPOSED: buf[n*128 + k] = bf16(W[k][n])
__device__ __align__(16) __nv_bfloat16 g_wh1[16384];
__device__ __align__(16) __nv_bfloat16 g_wl1[16384];
__device__ __align__(16) __nv_bfloat16 g_wh2[16384];
__device__ __align__(16) __nv_bfloat16 g_wl2[16384];

// per-block edge-index dtype detection (int64 values < 2^31 => odd words 0)
__device__ __forceinline__ int detect_is64(const int* __restrict__ ei) {
    int all0 = 1;
    for (int j = 0; j < 64; ++j)
        if (ei[2 * j + 1] != 0) { all0 = 0; break; }
    return all0;
}

__device__ __forceinline__ int load_idx(const int* __restrict__ ei, size_t pos, int is64) {
    return is64 ? ei[2 * pos] : ei[pos];
}

__device__ __forceinline__ unsigned pack_bf2(__nv_bfloat16 lo, __nv_bfloat16 hi) {
    return ((unsigned)__bfloat16_as_ushort(hi) << 16) | __bfloat16_as_ushort(lo);
}

// ------ W hi/lo conversion blocks + degree-count blocks (one launch) ------
__global__ void k_initcount(const int* __restrict__ ei,
                            const float* __restrict__ W1, const float* __restrict__ W2,
                            int E) {
    if (blockIdx.x < 128) {
        int i = blockIdx.x * 256 + threadIdx.x;     // 0..32767
        int mat = i >> 14;                          // 0: W1, 1: W2
        int idx = i & 16383;
        const float* W = mat ? W2 : W1;
        __nv_bfloat16* WH = mat ? g_wh2 : g_wh1;
        __nv_bfloat16* WL = mat ? g_wl2 : g_wl1;
        int k = idx >> 7, j = idx & 127;
        float w = W[idx];                           // W[k][j]
        __nv_bfloat16 h = __float2bfloat16_rn(w);
        __nv_bfloat16 l = __float2bfloat16_rn(w - __bfloat162float(h));
        WH[j * 128 + k] = h;                        // transposed [n][k]
        WL[j * 128 + k] = l;
        if (blockIdx.x == 0 && threadIdx.x == 0) g_total = 0;
    } else {
        __shared__ int s_is64;
        if (threadIdx.x == 0) s_is64 = detect_is64(ei);
        __syncthreads();
        int is64 = s_is64;
        int e0 = ((int)blockIdx.x - 128) * 1024 + threadIdx.x * 4;
#pragma unroll
        for (int q = 0; q < 4; ++q) {
            int e = e0 + q;
            if (e < E) atomicAdd(&g_deg[load_idx(ei, (size_t)E + e, is64)], 1);
        }
    }
}

// ---------------- parallel CSR slot allocation + dinv ---------------------
__global__ void k_alloc(int n) {
    int i    = blockIdx.x * blockDim.x + threadIdx.x;
    int lane = threadIdx.x & 31;
    int v = (i < n) ? g_deg[i] : 0;        // edges for this node

    int pfx = v;
#pragma unroll
    for (int o = 1; o < 32; o <<= 1) {
        int t = __shfl_up_sync(0xffffffff, pfx, o);
        if (lane >= o) pfx += t;
    }
    int wtotal = __shfl_sync(0xffffffff, pfx, 31);
    int excl   = pfx - v;

    int base = 0;
    if (lane == 31) base = atomicAdd(&g_total, wtotal);
    base = __shfl_sync(0xffffffff, base, 31);

    if (i < n) {
        int run = base + excl;
        g_rowstart[i] = run;
        g_cur[i]      = run;
        g_dinv[i]     = rsqrtf((float)(v + 1));   // +1 self-loop
    }
}

// ---------------- HMMA GEMM body (2m x 4n warp grid) ----------------
#define AS 68                      // uint stride per smem row
#define SM_AH 0
#define SM_AL 4352                 // 64*68
#define SM_BH 8704
#define SM_BL 17408                // 8704 + 128*68
#define SM_UINTS 26112
#define SM_BYTES (SM_UINTS * 4)

__device__ __forceinline__ void mma_bf16(float4& d,
                                         unsigned a0, unsigned a1, unsigned a2, unsigned a3,
                                         unsigned b0, unsigned b1) {
    asm volatile(
        "mma.sync.aligned.m16n8k16.row.col.f32.bf16.bf16.f32 "
        "{%0,%1,%2,%3}, {%4,%5,%6,%7}, {%8,%9}, {%0,%1,%2,%3};"
        : "+f"(d.x), "+f"(d.y), "+f"(d.z), "+f"(d.w)
        : "r"(a0), "r"(a1), "r"(a2), "r"(a3), "r"(b0), "r"(b1));
}

// epilogue always scales output rows by g_dinv[row] (dinv ready before both gemms)
__device__ __forceinline__ void gemm_body(
        int bid, unsigned* sm,
        const float* __restrict__ A,
        const __nv_bfloat16* __restrict__ WHT,
        const __nv_bfloat16* __restrict__ WLT,
        __half* __restrict__ C, int M) {
    unsigned* AH = sm + SM_AH;
    unsigned* AL = sm + SM_AL;
    unsigned* BH = sm + SM_BH;
    unsigned* BL = sm + SM_BL;

    int tid = threadIdx.x;
    int rowBase = bid * 64;

    // ---- copy W tiles ----
    {
        const uint4* gh = (const uint4*)WHT;
        const uint4* gl = (const uint4*)WLT;
        for (int i = tid; i < 2048; i += 256) {
            int nrow = i >> 4;
            int kk   = (i & 15) * 4;
            *(uint4*)&BH[nrow * AS + kk] = gh[i];
            *(uint4*)&BL[nrow * AS + kk] = gl[i];
        }
    }

    // ---- A tile: fp32 -> bf16 hi/lo into padded smem ----
    {
        int r  = tid >> 2;
        int t4 = tid & 3;
        int rg = rowBase + r;
        const float4* A4 = (const float4*)A;
#pragma unroll
        for (int i = 0; i < 8; ++i) {
            float4 v = make_float4(0.f, 0.f, 0.f, 0.f);
            if (rg < M) v = A4[(size_t)rg * 32 + t4 * 8 + i];
            __nv_bfloat16 h0 = __float2bfloat16_rn(v.x), h1 = __float2bfloat16_rn(v.y);
            __nv_bfloat16 h2 = __float2bfloat16_rn(v.z), h3 = __float2bfloat16_rn(v.w);
            __nv_bfloat16 l0 = __float2bfloat16_rn(v.x - __bfloat162float(h0));
            __nv_bfloat16 l1 = __float2bfloat16_rn(v.y - __bfloat162float(h1));
            __nv_bfloat16 l2 = __float2bfloat16_rn(v.z - __bfloat162float(h2));
            __nv_bfloat16 l3 = __float2bfloat16_rn(v.w - __bfloat162float(h3));
            int w = r * AS + t4 * 16 + i * 2;
            AH[w]     = pack_bf2(h0, h1);
            AH[w + 1] = pack_bf2(h2, h3);
            AL[w]     = pack_bf2(l0, l1);
            AL[w + 1] = pack_bf2(l2, l3);
        }
    }
    __syncthreads();

    // ---- compute: warp grid 2m x 4n, warp tile = 32 rows x 32 cols ----
    int wid = tid >> 5, lane = tid & 31;
    int wm = wid & 1, wn = wid >> 1;
    int g = lane >> 2, tig = lane & 3;

    float4 acc[2][4];
#pragma unroll
    for (int mt = 0; mt < 2; ++mt)
#pragma unroll
        for (int nt = 0; nt < 4; ++nt) acc[mt][nt] = make_float4(0.f, 0.f, 0.f, 0.f);

#pragma unroll
    for (int ks = 0; ks < 8; ++ks) {
        int ka = ks * 8 + tig;
        unsigned ah[2][4], al[2][4];
#pragma unroll
        for (int mt = 0; mt < 2; ++mt) {
            int ar0 = (wm * 32 + mt * 16 + g) * AS;
            int ar1 = ar0 + 8 * AS;
            ah[mt][0] = AH[ar0 + ka];     ah[mt][1] = AH[ar1 + ka];
            ah[mt][2] = AH[ar0 + ka + 4]; ah[mt][3] = AH[ar1 + ka + 4];
            al[mt][0] = AL[ar0 + ka];     al[mt][1] = AL[ar1 + ka];
            al[mt][2] = AL[ar0 + ka + 4]; al[mt][3] = AL[ar1 + ka + 4];
        }
        unsigned bh[4][2], bl[4][2];
#pragma unroll
        for (int nt = 0; nt < 4; ++nt) {
            int br = (wn * 32 + nt * 8 + g) * AS + ka;
            bh[nt][0] = BH[br]; bh[nt][1] = BH[br + 4];
            bl[nt][0] = BL[br]; bl[nt][1] = BL[br + 4];
        }
#pragma unroll
        for (int mt = 0; mt < 2; ++mt)
#pragma unroll
            for (int nt = 0; nt < 4; ++nt) {
                mma_bf16(acc[mt][nt], ah[mt][0], ah[mt][1], ah[mt][2], ah[mt][3],
                         bh[nt][0], bh[nt][1]);
                mma_bf16(acc[mt][nt], al[mt][0], al[mt][1], al[mt][2], al[mt][3],
                         bh[nt][0], bh[nt][1]);
                mma_bf16(acc[mt][nt], ah[mt][0], ah[mt][1], ah[mt][2], ah[mt][3],
                         bl[nt][0], bl[nt][1]);
            }
    }

    // ---- epilogue: scale rows by dinv, convert fp16 ----
#pragma unroll
    for (int mt = 0; mt < 2; ++mt) {
        int r0 = rowBase + wm * 32 + mt * 16 + g;
        int r1 = r0 + 8;
        float s0 = (r0 < M) ? g_dinv[r0] : 0.f;
        float s1 = (r1 < M) ? g_dinv[r1] : 0.f;
#pragma unroll
        for (int nt = 0; nt < 4; ++nt) {
            int col = wn * 32 + nt * 8 + tig * 2;
            if (r0 < M)
                *(__half2*)(C + (size_t)r0 * 128 + col) =
                    __floats2half2_rn(acc[mt][nt].x * s0, acc[mt][nt].y * s0);
            if (r1 < M)
                *(__half2*)(C + (size_t)r1 * 128 + col) =
                    __floats2half2_rn(acc[mt][nt].z * s1, acc[mt][nt].w * s1);
        }
    }
}

// ---- mega: GEMM1 (dinv-scaled), then each block fills its CSR slice ------
__global__ __launch_bounds__(256) void k_mega(
        const float* __restrict__ A,
        const __nv_bfloat16* __restrict__ WHT,
        const __nv_bfloat16* __restrict__ WLT,
        __half* __restrict__ C, int M,
        const int* __restrict__ ei, int E) {
    extern __shared__ unsigned sm[];
    __shared__ int s_is64;

    gemm_body(blockIdx.x, sm, A, WHT, WLT, C, M);

    if (threadIdx.x == 0) s_is64 = detect_is64(ei);
    __syncthreads();
    int is64 = s_is64;
    int e0 = blockIdx.x * 1024 + threadIdx.x * 4;
#pragma unroll
    for (int q = 0; q < 4; ++q) {
        int e = e0 + q;
        if (e < E) {
            int s = load_idx(ei, (size_t)e, is64);
            int d = load_idx(ei, (size_t)E + e, is64);
            int pos = atomicAdd(&g_cur[d], 1);
            g_esrc[pos] = s;
        }
    }
}

__global__ __launch_bounds__(256) void k_gemm2(
        const float* __restrict__ A,
        const __nv_bfloat16* __restrict__ WHT,
        const __nv_bfloat16* __restrict__ WLT,
        __half* __restrict__ C, int M) {
    extern __shared__ unsigned sm[];
    gemm_body(blockIdx.x, sm, A, WHT, WLT, C, M);
}

// ---------------- pure gather-add aggregation + bias + ReLU ---------------
// H rows pre-scaled by dinv[src] (both layers). One warp per dst node,
// lane owns 4 cols (uint2). Pairwise fp16 HADD2 pre-reduction halves the
// convert/add instruction count (kernel is issue-bound per ncu R14).
__device__ __forceinline__ void add_h4(float4& acc, uint2 raw) {
    __half2* ph = (__half2*)&raw;
    float2 lo = __half22float2(ph[0]);
    float2 hi = __half22float2(ph[1]);
    acc.x += lo.x; acc.y += lo.y; acc.z += hi.x; acc.w += hi.y;
}

__device__ __forceinline__ uint2 hadd2_pair(uint2 a, uint2 b) {
    __half2* pa = (__half2*)&a;
    __half2* pb = (__half2*)&b;
    uint2 r;
    *(__half2*)&r.x = __hadd2(pa[0], pb[0]);
    *(__half2*)&r.y = __hadd2(pa[1], pb[1]);
    return r;
}

__global__ void k_agg(const __half* __restrict__ H,
                      const float* __restrict__ b,
                      float* __restrict__ out, int n) {
    int warp = (int)((blockIdx.x * (size_t)blockDim.x + threadIdx.x) >> 5);
    int lane = threadIdx.x & 31;
    if (warp >= n) return;
    unsigned node = (unsigned)warp;

    const uint2* H2 = (const uint2*)H;   // 32 uint2 per row; 32-bit offsets OK (<2^31)

    float4 acc = make_float4(0.f, 0.f, 0.f, 0.f);
    add_h4(acc, H2[node * 32u + lane]);  // self-loop (pre-scaled)

    int p   = g_rowstart[node];
    int end = p + g_deg[node];

    for (; p + 3 < end; p += 4) {
        unsigned s0 = (unsigned)g_esrc[p],     s1 = (unsigned)g_esrc[p + 1];
        unsigned s2 = (unsigned)g_esrc[p + 2], s3 = (unsigned)g_esrc[p + 3];
        uint2 v0 = H2[s0 * 32u + lane];
        uint2 v1 = H2[s1 * 32u + lane];
        uint2 v2 = H2[s2 * 32u + lane];
        uint2 v3 = H2[s3 * 32u + lane];
        uint2 w01 = hadd2_pair(v0, v1);      // fp16 pairwise pre-reduce
        uint2 w23 = hadd2_pair(v2, v3);
        add_h4(acc, w01);
        add_h4(acc, w23);
    }
    if (p + 1 < end) {
        unsigned s0 = (unsigned)g_esrc[p], s1 = (unsigned)g_esrc[p + 1];
        uint2 w = hadd2_pair(H2[s0 * 32u + lane], H2[s1 * 32u + lane]);
        add_h4(acc, w);
        p += 2;
    }
    if (p < end) {
        unsigned s0 = (unsigned)g_esrc[p];
        add_h4(acc, H2[s0 * 32u + lane]);
    }

    float di = g_dinv[node];
    float4 bv = ((const float4*)b)[lane];
    float4 r;
    r.x = fmaxf(fmaf(di, acc.x, bv.x), 0.f);
    r.y = fmaxf(fmaf(di, acc.y, bv.y), 0.f);
    r.z = fmaxf(fmaf(di, acc.z, bv.z), 0.f);
    r.w = fmaxf(fmaf(di, acc.w, bv.w), 0.f);
    ((float4*)out)[node * 32u + lane] = r;
}

// ---------------- launch ----------------
extern "C" void kernel_launch(void* const* d_in, const int* in_sizes, int n_in,
                              void* d_out, int out_size) {
    const float* x  = (const float*)d_in[0];
    const int*   ei = (const int*)d_in[1];
    const float* W1 = (const float*)d_in[2];
    const float* b1 = (const float*)d_in[3];
    const float* W2 = (const float*)d_in[4];
    const float* b2 = (const float*)d_in[5];
    float* out = (float*)d_out;

    int n = in_sizes[0] / D;        // 50000
    int E = in_sizes[1] / 2;        // 800000

    __half* h;  float* a;  int* degPtr;
    __nv_bfloat16 *wh1, *wl1, *wh2, *wl2;
    cudaGetSymbolAddress((void**)&h,      g_h);
    cudaGetSymbolAddress((void**)&a,      g_a);
    cudaGetSymbolAddress((void**)&degPtr, g_deg);
    cudaGetSymbolAddress((void**)&wh1, g_wh1);
    cudaGetSymbolAddress((void**)&wl1, g_wl1);
    cudaGetSymbolAddress((void**)&wh2, g_wh2);
    cudaGetSymbolAddress((void**)&wl2, g_wl2);

    cudaFuncSetAttribute(k_mega,  cudaFuncAttributeMaxDynamicSharedMemorySize, SM_BYTES);
    cudaFuncSetAttribute(k_gemm2, cudaFuncAttributeMaxDynamicSharedMemorySize, SM_BYTES);

    int countBlocks = (E + 1023) / 1024;   // 4 edges/thread
    int aggBlocks   = (n * 32 + 255) / 256;
    int gemmBlocks  = (n + 63) / 64;       // 782 (each also fills 1024 edges)
    int nodeBlocks  = (n + 255) / 256;

    // zero degrees (captured async memset)
    cudaMemsetAsync(degPtr, 0, (size_t)n * sizeof(int));
    // W hi/lo conversion blocks + degree-count blocks
    k_initcount<<<128 + countBlocks, 256>>>(ei, W1, W2, E);
    // CSR slot allocation + dinv (dinv ready BEFORE gemm1)
    k_alloc<<<nodeBlocks, 256>>>(n);
    // GEMM1 (rows pre-scaled by dinv) with per-block CSR fill tail
    k_mega<<<gemmBlocks, 256, SM_BYTES>>>(x, wh1, wl1, h, n, ei, E);
    // layer-1 aggregation (pure gather-add)
    k_agg<<<aggBlocks, 256>>>(h, b1, a, n);
    // layer-2 GEMM (rows pre-scaled by dinv) + pure gather-add agg
    k_gemm2<<<gemmBlocks, 256, SM_BYTES>>>(a, wh2, wl2, h, n);
    k_agg<<<aggBlocks, 256>>>(h, b2, out, n);
}